// round 1
// baseline (speedup 1.0000x reference)
#include <cuda_runtime.h>
#include <cuda_bf16.h>
#include <math.h>

// ---------------------------------------------------------------------------
// GAT 3-layer forward on GB300.
// Structure per layer:
//   feat = H_in @ W                (SGEMM, fp32)
//   el[n,h] = feat[n,h,:].al[h]    er likewise            (warp-per-node)
//   e_edge = leakyrelu(el[src]+er[dst]); softmax over incoming edges of dst;
//   rst[dst] = sum_e a_e * feat[src_e] + b  (relu for layers 1,2)
// Aggregation uses CSR-by-dst built on-device each call (no fp32 atomics).
// ---------------------------------------------------------------------------

#define MAXN 50000
#define MAXE 800000

__device__ float g_feat[MAXN * 256];
__device__ float g_bufA[MAXN * 256];
__device__ float g_bufB[MAXN * 256];
__device__ float g_el[MAXN * 4];
__device__ float g_er[MAXN * 4];
__device__ int   g_rowptr[MAXN + 1];
__device__ int   g_cursor[MAXN];
__device__ int   g_cnt[MAXN];
__device__ int   g_colsrc[MAXE];

// ---------------------------------------------------------------------------
// CSR build
// ---------------------------------------------------------------------------
__global__ void hist_kernel(const int* __restrict__ dst, int* __restrict__ cnt, int E) {
    int i = blockIdx.x * blockDim.x + threadIdx.x;
    if (i < E) atomicAdd(&cnt[dst[i]], 1);
}

__global__ void scan_kernel(const int* __restrict__ cnt, int* __restrict__ rowptr,
                            int* __restrict__ cursor, int N, int E) {
    __shared__ int sums[1024];
    int tid = threadIdx.x;
    int chunk = (N + 1023) >> 10;
    int start = tid * chunk;
    int end = min(start + chunk, N);
    int s = 0;
    for (int i = start; i < end; i++) s += cnt[i];
    sums[tid] = s;
    __syncthreads();
    for (int off = 1; off < 1024; off <<= 1) {
        int v = (tid >= off) ? sums[tid - off] : 0;
        __syncthreads();
        sums[tid] += v;
        __syncthreads();
    }
    int run = sums[tid] - s;  // exclusive prefix
    for (int i = start; i < end; i++) {
        rowptr[i] = run;
        cursor[i] = run;
        run += cnt[i];
    }
    if (tid == 0) rowptr[N] = E;
}

__global__ void scatter_kernel(const int* __restrict__ src, const int* __restrict__ dst,
                               int* __restrict__ cursor, int* __restrict__ colsrc, int E) {
    int i = blockIdx.x * blockDim.x + threadIdx.x;
    if (i < E) {
        int p = atomicAdd(&cursor[dst[i]], 1);
        colsrc[p] = src[i];
    }
}

// ---------------------------------------------------------------------------
// SGEMM: C[M,Nc] = A[M,K] @ B[K,Nc], row-major, fp32.
// BM=128, BN=64, BK=16, 256 threads, 8x4 microtile.
// Requires K % 16 == 0, Nc % 64 == 0 (true here: K in {128,256}, Nc in {256,64}).
// ---------------------------------------------------------------------------
__global__ __launch_bounds__(256) void sgemm_kernel(
    const float* __restrict__ A, const float* __restrict__ B, float* __restrict__ C,
    int M, int K, int Nc) {
    __shared__ float As[16][128];
    __shared__ float Bs[16][64];
    const int t = threadIdx.x;
    const int m0 = blockIdx.y * 128;
    const int n0 = blockIdx.x * 64;
    const int ty = t >> 4;    // 0..15  -> rows ty*8..ty*8+7
    const int tx = t & 15;    // 0..15  -> cols tx*4..tx*4+3
    const int arow = t >> 2;        // 0..63
    const int akc  = (t & 3) * 4;   // 0,4,8,12
    const int brow = t >> 4;        // 0..15
    const int bcol = (t & 15) * 4;  // 0..60

    float acc[8][4];
    #pragma unroll
    for (int i = 0; i < 8; i++)
        #pragma unroll
        for (int j = 0; j < 4; j++) acc[i][j] = 0.f;

    for (int k0 = 0; k0 < K; k0 += 16) {
        #pragma unroll
        for (int l = 0; l < 2; l++) {
            int r = arow + l * 64;
            float4 v = make_float4(0.f, 0.f, 0.f, 0.f);
            if (m0 + r < M)
                v = *(const float4*)&A[(size_t)(m0 + r) * K + k0 + akc];
            As[akc + 0][r] = v.x;
            As[akc + 1][r] = v.y;
            As[akc + 2][r] = v.z;
            As[akc + 3][r] = v.w;
        }
        float4 bv = *(const float4*)&B[(size_t)(k0 + brow) * Nc + n0 + bcol];
        *(float4*)&Bs[brow][bcol] = bv;
        __syncthreads();
        #pragma unroll
        for (int kk = 0; kk < 16; kk++) {
            float4 b4 = *(float4*)&Bs[kk][tx * 4];
            float4 a0 = *(float4*)&As[kk][ty * 8];
            float4 a1 = *(float4*)&As[kk][ty * 8 + 4];
            float av[8] = {a0.x, a0.y, a0.z, a0.w, a1.x, a1.y, a1.z, a1.w};
            #pragma unroll
            for (int i = 0; i < 8; i++) {
                acc[i][0] += av[i] * b4.x;
                acc[i][1] += av[i] * b4.y;
                acc[i][2] += av[i] * b4.z;
                acc[i][3] += av[i] * b4.w;
            }
        }
        __syncthreads();
    }
    #pragma unroll
    for (int i = 0; i < 8; i++) {
        int r = m0 + ty * 8 + i;
        if (r < M) {
            float4 o = make_float4(acc[i][0], acc[i][1], acc[i][2], acc[i][3]);
            *(float4*)&C[(size_t)r * Nc + n0 + tx * 4] = o;
        }
    }
}

// ---------------------------------------------------------------------------
// el/er: per-node per-head dot products with attention vectors.
// One warp per node.
// ---------------------------------------------------------------------------
template <int H, int D>
__global__ void elr_kernel(const float* __restrict__ feat, const float* __restrict__ al,
                           const float* __restrict__ ar, float* __restrict__ el,
                           float* __restrict__ er, int N) {
    int warp = (blockIdx.x * blockDim.x + threadIdx.x) >> 5;
    int lane = threadIdx.x & 31;
    if (warp >= N) return;
    const float* f = feat + (size_t)warp * H * D;
    #pragma unroll
    for (int h = 0; h < H; h++) {
        float sl = 0.f, sr = 0.f;
        #pragma unroll
        for (int c0 = 0; c0 < D; c0 += 32) {
            int c = c0 + lane;
            float v = f[h * D + c];
            sl += v * al[h * D + c];
            sr += v * ar[h * D + c];
        }
        #pragma unroll
        for (int o = 16; o; o >>= 1) {
            sl += __shfl_xor_sync(0xffffffffu, sl, o);
            sr += __shfl_xor_sync(0xffffffffu, sr, o);
        }
        if (lane == 0) {
            el[(size_t)warp * H + h] = sl;
            er[(size_t)warp * H + h] = sr;
        }
    }
}

__device__ __forceinline__ float lrelu(float x) { return x > 0.f ? x : 0.2f * x; }

// ---------------------------------------------------------------------------
// Fused edge-softmax + aggregation: one warp per dst node.
// Pass 1: per-head max of leakyrelu(el[src]+er[dst]) over incoming edges.
// Pass 2: sum of exp(x - max).
// Pass 3: weighted accumulate feat[src], write out (+bias, relu?).
// ---------------------------------------------------------------------------
template <int H, int D, bool RELU>
__global__ __launch_bounds__(256) void agg_kernel(
    const float* __restrict__ feat, const float* __restrict__ el,
    const float* __restrict__ er, const float* __restrict__ bias,
    const int* __restrict__ rowptr, const int* __restrict__ colsrc,
    float* __restrict__ out, int N) {
    constexpr int HD = H * D;
    const unsigned FULL = 0xffffffffu;
    int warp = (blockIdx.x * blockDim.x + threadIdx.x) >> 5;
    int lane = threadIdx.x & 31;
    if (warp >= N) return;
    const int n = warp;
    const int base = rowptr[n];
    const int deg = rowptr[n + 1] - base;

    float erl = (lane < H) ? er[(size_t)n * H + lane] : 0.f;
    float erh[H];
    #pragma unroll
    for (int h = 0; h < H; h++) erh[h] = __shfl_sync(FULL, erl, h);

    float mh[H], sh[H];
    #pragma unroll
    for (int h = 0; h < H; h++) { mh[h] = -1e30f; sh[h] = 0.f; }

    // Pass 1: max per head
    for (int i0 = 0; i0 < deg; i0 += 32) {
        int i = i0 + lane;
        bool act = i < deg;
        int s = colsrc[base + (act ? i : 0)];
        #pragma unroll
        for (int h = 0; h < H; h++) {
            float x = lrelu(el[(size_t)s * H + h] + erh[h]);
            if (act) mh[h] = fmaxf(mh[h], x);
        }
    }
    #pragma unroll
    for (int h = 0; h < H; h++) {
        float v = mh[h];
        #pragma unroll
        for (int o = 16; o; o >>= 1) v = fmaxf(v, __shfl_xor_sync(FULL, v, o));
        mh[h] = v;
    }
    // Pass 2: sum of exp
    for (int i0 = 0; i0 < deg; i0 += 32) {
        int i = i0 + lane;
        bool act = i < deg;
        int s = colsrc[base + (act ? i : 0)];
        #pragma unroll
        for (int h = 0; h < H; h++) {
            float x = lrelu(el[(size_t)s * H + h] + erh[h]);
            float w = act ? expf(x - mh[h]) : 0.f;
            sh[h] += w;
        }
    }
    #pragma unroll
    for (int h = 0; h < H; h++) {
        float v = sh[h];
        #pragma unroll
        for (int o = 16; o; o >>= 1) v += __shfl_xor_sync(FULL, v, o);
        sh[h] = 1.f / v;  // inverse; unused if deg == 0
    }

    // Pass 3: weighted accumulation of feat[src]
    if constexpr (HD == 256) {
        const int c0 = lane * 4, c1 = 128 + lane * 4;
        const int h0 = lane >> 4;       // head for chunk0: 0 or 1
        const int h1 = 2 + (lane >> 4); // head for chunk1: 2 or 3
        const float er0 = (lane < 16) ? erh[0] : erh[1];
        const float m0v = (lane < 16) ? mh[0] : mh[1];
        const float is0 = (lane < 16) ? sh[0] : sh[1];
        const float er1 = (lane < 16) ? erh[2] : erh[3];
        const float m1v = (lane < 16) ? mh[2] : mh[3];
        const float is1 = (lane < 16) ? sh[2] : sh[3];
        float4 a0 = make_float4(0.f, 0.f, 0.f, 0.f);
        float4 a1 = make_float4(0.f, 0.f, 0.f, 0.f);
        for (int i = 0; i < deg; i++) {
            int s = colsrc[base + i];
            const float* fs = feat + (size_t)s * 256;
            float x0 = lrelu(el[(size_t)s * 4 + h0] + er0);
            float w0 = expf(x0 - m0v) * is0;
            float x1 = lrelu(el[(size_t)s * 4 + h1] + er1);
            float w1 = expf(x1 - m1v) * is1;
            float4 f0 = *(const float4*)&fs[c0];
            float4 f1 = *(const float4*)&fs[c1];
            a0.x += f0.x * w0; a0.y += f0.y * w0; a0.z += f0.z * w0; a0.w += f0.w * w0;
            a1.x += f1.x * w1; a1.y += f1.y * w1; a1.z += f1.z * w1; a1.w += f1.w * w1;
        }
        float4 b0 = *(const float4*)&bias[c0];
        float4 b1 = *(const float4*)&bias[c1];
        a0.x += b0.x; a0.y += b0.y; a0.z += b0.z; a0.w += b0.w;
        a1.x += b1.x; a1.y += b1.y; a1.z += b1.z; a1.w += b1.w;
        if (RELU) {
            a0.x = fmaxf(a0.x, 0.f); a0.y = fmaxf(a0.y, 0.f);
            a0.z = fmaxf(a0.z, 0.f); a0.w = fmaxf(a0.w, 0.f);
            a1.x = fmaxf(a1.x, 0.f); a1.y = fmaxf(a1.y, 0.f);
            a1.z = fmaxf(a1.z, 0.f); a1.w = fmaxf(a1.w, 0.f);
        }
        *(float4*)&out[(size_t)n * 256 + c0] = a0;
        *(float4*)&out[(size_t)n * 256 + c1] = a1;
    } else {  // HD == 64, H == 1
        const int c0 = lane * 2;
        float2 a = make_float2(0.f, 0.f);
        for (int i = 0; i < deg; i++) {
            int s = colsrc[base + i];
            float x = lrelu(el[s] + erh[0]);
            float w = expf(x - mh[0]) * sh[0];
            float2 f = *(const float2*)&feat[(size_t)s * 64 + c0];
            a.x += f.x * w;
            a.y += f.y * w;
        }
        a.x += bias[c0];
        a.y += bias[c0 + 1];
        if (RELU) { a.x = fmaxf(a.x, 0.f); a.y = fmaxf(a.y, 0.f); }
        *(float2*)&out[(size_t)n * 64 + c0] = a;
    }
}

// ---------------------------------------------------------------------------
// kernel_launch
// ---------------------------------------------------------------------------
extern "C" void kernel_launch(void* const* d_in, const int* in_sizes, int n_in,
                              void* d_out, int out_size) {
    const float* features = (const float*)d_in[0];
    const int*   src      = (const int*)d_in[1];
    const int*   dst      = (const int*)d_in[2];
    const float* W1  = (const float*)d_in[3];
    const float* al1 = (const float*)d_in[4];
    const float* ar1 = (const float*)d_in[5];
    const float* b1  = (const float*)d_in[6];
    const float* W2  = (const float*)d_in[7];
    const float* al2 = (const float*)d_in[8];
    const float* ar2 = (const float*)d_in[9];
    const float* b2  = (const float*)d_in[10];
    const float* W3  = (const float*)d_in[11];
    const float* al3 = (const float*)d_in[12];
    const float* ar3 = (const float*)d_in[13];
    const float* b3  = (const float*)d_in[14];

    const int N = in_sizes[0] / 128;
    const int E = in_sizes[1];

    float *feat, *bufA, *bufB, *el, *er;
    int *rowptr, *cursor, *cnt, *colsrc;
    cudaGetSymbolAddress((void**)&feat,   g_feat);
    cudaGetSymbolAddress((void**)&bufA,   g_bufA);
    cudaGetSymbolAddress((void**)&bufB,   g_bufB);
    cudaGetSymbolAddress((void**)&el,     g_el);
    cudaGetSymbolAddress((void**)&er,     g_er);
    cudaGetSymbolAddress((void**)&rowptr, g_rowptr);
    cudaGetSymbolAddress((void**)&cursor, g_cursor);
    cudaGetSymbolAddress((void**)&cnt,    g_cnt);
    cudaGetSymbolAddress((void**)&colsrc, g_colsrc);

    // --- CSR by dst ---
    cudaMemsetAsync(cnt, 0, (size_t)N * sizeof(int));
    hist_kernel<<<(E + 255) / 256, 256>>>(dst, cnt, E);
    scan_kernel<<<1, 1024>>>(cnt, rowptr, cursor, N, E);
    scatter_kernel<<<(E + 255) / 256, 256>>>(src, dst, cursor, colsrc, E);

    const int warpsGrid = (N + 7) / 8;  // 8 warps (256 thr) per block

    // --- Layer 1: IN=128 -> H*D=256 ---
    {
        dim3 grid(256 / 64, (N + 127) / 128);
        sgemm_kernel<<<grid, 256>>>(features, W1, feat, N, 128, 256);
        elr_kernel<4, 64><<<warpsGrid, 256>>>(feat, al1, ar1, el, er, N);
        agg_kernel<4, 64, true><<<warpsGrid, 256>>>(feat, el, er, b1, rowptr, colsrc, bufA, N);
    }
    // --- Layer 2: 256 -> 256 ---
    {
        dim3 grid(256 / 64, (N + 127) / 128);
        sgemm_kernel<<<grid, 256>>>(bufA, W2, feat, N, 256, 256);
        elr_kernel<4, 64><<<warpsGrid, 256>>>(feat, al2, ar2, el, er, N);
        agg_kernel<4, 64, true><<<warpsGrid, 256>>>(feat, el, er, b2, rowptr, colsrc, bufB, N);
    }
    // --- Layer 3: 256 -> 64 (H=1); mean over 1 head == identity ---
    {
        dim3 grid(64 / 64, (N + 127) / 128);
        sgemm_kernel<<<grid, 256>>>(bufB, W3, feat, N, 256, 64);
        elr_kernel<1, 64><<<warpsGrid, 256>>>(feat, al3, ar3, el, er, N);
        agg_kernel<1, 64, false><<<warpsGrid, 256>>>(feat, el, er, b3, rowptr, colsrc,
                                                     (float*)d_out, N);
    }
}

// round 2
// speedup vs baseline: 1.0245x; 1.0245x over previous
#include <cuda_runtime.h>
#include <cuda_bf16.h>
#include <math.h>

// ---------------------------------------------------------------------------
// GAT 3-layer forward on GB300.
//   feat = H_in @ W                (SGEMM, fp32)
//   el/er per-node per-head dots   (warp-per-node)
//   edge softmax over incoming edges per dst (CSR-by-dst, warp-per-node):
//     pass1: per-head max
//     pass2: e = exp(x - m) stored to ew[], per-head sum
//     pass3: out[dst] = sum_e (e * inv_s) * feat[src] + b  (relu layers 1,2)
// ---------------------------------------------------------------------------

#define MAXN 50000
#define MAXE 800000

__device__ float g_feat[MAXN * 256];
__device__ float g_bufA[MAXN * 256];
__device__ float g_bufB[MAXN * 256];
__device__ float g_el[MAXN * 4];
__device__ float g_er[MAXN * 4];
__device__ float g_ew[MAXE * 4];      // per-edge, per-head exp values
__device__ int   g_rowptr[MAXN + 1];
__device__ int   g_cursor[MAXN];
__device__ int   g_cnt[MAXN];
__device__ int   g_colsrc[MAXE];

// ---------------------------------------------------------------------------
// CSR build
// ---------------------------------------------------------------------------
__global__ void hist_kernel(const int* __restrict__ dst, int* __restrict__ cnt, int E) {
    int i = blockIdx.x * blockDim.x + threadIdx.x;
    if (i < E) atomicAdd(&cnt[dst[i]], 1);
}

__global__ void scan_kernel(const int* __restrict__ cnt, int* __restrict__ rowptr,
                            int* __restrict__ cursor, int N, int E) {
    __shared__ int sums[1024];
    int tid = threadIdx.x;
    int chunk = (N + 1023) >> 10;
    int start = tid * chunk;
    int end = min(start + chunk, N);
    int s = 0;
    for (int i = start; i < end; i++) s += cnt[i];
    sums[tid] = s;
    __syncthreads();
    for (int off = 1; off < 1024; off <<= 1) {
        int v = (tid >= off) ? sums[tid - off] : 0;
        __syncthreads();
        sums[tid] += v;
        __syncthreads();
    }
    int run = sums[tid] - s;  // exclusive prefix
    for (int i = start; i < end; i++) {
        rowptr[i] = run;
        cursor[i] = run;
        run += cnt[i];
    }
    if (tid == 0) rowptr[N] = E;
}

__global__ void scatter_kernel(const int* __restrict__ src, const int* __restrict__ dst,
                               int* __restrict__ cursor, int* __restrict__ colsrc, int E) {
    int i = blockIdx.x * blockDim.x + threadIdx.x;
    if (i < E) {
        int p = atomicAdd(&cursor[dst[i]], 1);
        colsrc[p] = src[i];
    }
}

// ---------------------------------------------------------------------------
// SGEMM: C[M,Nc] = A[M,K] @ B[K,Nc], row-major, fp32.
// BM=128, BN=64, BK=16, 256 threads, 8x4 microtile.
// ---------------------------------------------------------------------------
__global__ __launch_bounds__(256) void sgemm_kernel(
    const float* __restrict__ A, const float* __restrict__ B, float* __restrict__ C,
    int M, int K, int Nc) {
    __shared__ float As[16][128];
    __shared__ float Bs[16][64];
    const int t = threadIdx.x;
    const int m0 = blockIdx.y * 128;
    const int n0 = blockIdx.x * 64;
    const int ty = t >> 4;
    const int tx = t & 15;
    const int arow = t >> 2;
    const int akc  = (t & 3) * 4;
    const int brow = t >> 4;
    const int bcol = (t & 15) * 4;

    float acc[8][4];
    #pragma unroll
    for (int i = 0; i < 8; i++)
        #pragma unroll
        for (int j = 0; j < 4; j++) acc[i][j] = 0.f;

    for (int k0 = 0; k0 < K; k0 += 16) {
        #pragma unroll
        for (int l = 0; l < 2; l++) {
            int r = arow + l * 64;
            float4 v = make_float4(0.f, 0.f, 0.f, 0.f);
            if (m0 + r < M)
                v = *(const float4*)&A[(size_t)(m0 + r) * K + k0 + akc];
            As[akc + 0][r] = v.x;
            As[akc + 1][r] = v.y;
            As[akc + 2][r] = v.z;
            As[akc + 3][r] = v.w;
        }
        float4 bv = *(const float4*)&B[(size_t)(k0 + brow) * Nc + n0 + bcol];
        *(float4*)&Bs[brow][bcol] = bv;
        __syncthreads();
        #pragma unroll
        for (int kk = 0; kk < 16; kk++) {
            float4 b4 = *(float4*)&Bs[kk][tx * 4];
            float4 a0 = *(float4*)&As[kk][ty * 8];
            float4 a1 = *(float4*)&As[kk][ty * 8 + 4];
            float av[8] = {a0.x, a0.y, a0.z, a0.w, a1.x, a1.y, a1.z, a1.w};
            #pragma unroll
            for (int i = 0; i < 8; i++) {
                acc[i][0] += av[i] * b4.x;
                acc[i][1] += av[i] * b4.y;
                acc[i][2] += av[i] * b4.z;
                acc[i][3] += av[i] * b4.w;
            }
        }
        __syncthreads();
    }
    #pragma unroll
    for (int i = 0; i < 8; i++) {
        int r = m0 + ty * 8 + i;
        if (r < M) {
            float4 o = make_float4(acc[i][0], acc[i][1], acc[i][2], acc[i][3]);
            *(float4*)&C[(size_t)r * Nc + n0 + tx * 4] = o;
        }
    }
}

// ---------------------------------------------------------------------------
// el/er: per-node per-head dot products with attention vectors. Warp-per-node.
// ---------------------------------------------------------------------------
template <int H, int D>
__global__ void elr_kernel(const float* __restrict__ feat, const float* __restrict__ al,
                           const float* __restrict__ ar, float* __restrict__ el,
                           float* __restrict__ er, int N) {
    int warp = (blockIdx.x * blockDim.x + threadIdx.x) >> 5;
    int lane = threadIdx.x & 31;
    if (warp >= N) return;
    const float* f = feat + (size_t)warp * H * D;
    #pragma unroll
    for (int h = 0; h < H; h++) {
        float sl = 0.f, sr = 0.f;
        #pragma unroll
        for (int c0 = 0; c0 < D; c0 += 32) {
            int c = c0 + lane;
            float v = f[h * D + c];
            sl += v * al[h * D + c];
            sr += v * ar[h * D + c];
        }
        #pragma unroll
        for (int o = 16; o; o >>= 1) {
            sl += __shfl_xor_sync(0xffffffffu, sl, o);
            sr += __shfl_xor_sync(0xffffffffu, sr, o);
        }
        if (lane == 0) {
            el[(size_t)warp * H + h] = sl;
            er[(size_t)warp * H + h] = sr;
        }
    }
}

__device__ __forceinline__ float lrelu(float x) { return x > 0.f ? x : 0.2f * x; }

// ---------------------------------------------------------------------------
// Fused edge-softmax + aggregation: one warp per dst node.
// ---------------------------------------------------------------------------
template <int H, int D, bool RELU>
__global__ __launch_bounds__(256) void agg_kernel(
    const float* __restrict__ feat, const float* __restrict__ el,
    const float* __restrict__ er, const float* __restrict__ bias,
    const int* __restrict__ rowptr, const int* __restrict__ colsrc,
    float* __restrict__ ew, float* __restrict__ out, int N) {
    constexpr int HD = H * D;
    const unsigned FULL = 0xffffffffu;
    int warp = (blockIdx.x * blockDim.x + threadIdx.x) >> 5;
    int lane = threadIdx.x & 31;
    if (warp >= N) return;
    const int n = warp;
    const int base = rowptr[n];
    const int deg = rowptr[n + 1] - base;

    float erl = (lane < H) ? er[(size_t)n * H + lane] : 0.f;
    float erh[H];
    #pragma unroll
    for (int h = 0; h < H; h++) erh[h] = __shfl_sync(FULL, erl, h);

    float mh[H], sh[H];
    #pragma unroll
    for (int h = 0; h < H; h++) { mh[h] = -1e30f; sh[h] = 0.f; }

    // Pass 1: max per head
    for (int i0 = 0; i0 < deg; i0 += 32) {
        int i = i0 + lane;
        bool act = i < deg;
        int s = colsrc[base + (act ? i : 0)];
        if constexpr (H == 4) {
            float4 e4 = *(const float4*)&el[(size_t)s * 4];
            if (act) {
                mh[0] = fmaxf(mh[0], lrelu(e4.x + erh[0]));
                mh[1] = fmaxf(mh[1], lrelu(e4.y + erh[1]));
                mh[2] = fmaxf(mh[2], lrelu(e4.z + erh[2]));
                mh[3] = fmaxf(mh[3], lrelu(e4.w + erh[3]));
            }
        } else {
            float x = lrelu(el[s] + erh[0]);
            if (act) mh[0] = fmaxf(mh[0], x);
        }
    }
    #pragma unroll
    for (int h = 0; h < H; h++) {
        float v = mh[h];
        #pragma unroll
        for (int o = 16; o; o >>= 1) v = fmaxf(v, __shfl_xor_sync(FULL, v, o));
        mh[h] = v;
    }

    // Pass 2: e = exp(x - m); store to ew; accumulate per-head sum
    for (int i0 = 0; i0 < deg; i0 += 32) {
        int i = i0 + lane;
        bool act = i < deg;
        int s = colsrc[base + (act ? i : 0)];
        if constexpr (H == 4) {
            float4 e4 = *(const float4*)&el[(size_t)s * 4];
            float w0 = __expf(lrelu(e4.x + erh[0]) - mh[0]);
            float w1 = __expf(lrelu(e4.y + erh[1]) - mh[1]);
            float w2 = __expf(lrelu(e4.z + erh[2]) - mh[2]);
            float w3 = __expf(lrelu(e4.w + erh[3]) - mh[3]);
            if (act) {
                sh[0] += w0; sh[1] += w1; sh[2] += w2; sh[3] += w3;
                *(float4*)&ew[(size_t)(base + i) * 4] = make_float4(w0, w1, w2, w3);
            }
        } else {
            float w = __expf(lrelu(el[s] + erh[0]) - mh[0]);
            if (act) {
                sh[0] += w;
                ew[base + i] = w;
            }
        }
    }
    #pragma unroll
    for (int h = 0; h < H; h++) {
        float v = sh[h];
        #pragma unroll
        for (int o = 16; o; o >>= 1) v += __shfl_xor_sync(FULL, v, o);
        sh[h] = 1.f / v;  // unused if deg == 0
    }

    // Pass 3: weighted accumulation of feat[src] using stored e values
    if constexpr (HD == 256) {
        const int c0 = lane * 4, c1 = 128 + lane * 4;
        const bool lo = (lane < 16);
        const float is0 = lo ? sh[0] : sh[1];
        const float is1 = lo ? sh[2] : sh[3];
        float4 a0 = make_float4(0.f, 0.f, 0.f, 0.f);
        float4 a1 = make_float4(0.f, 0.f, 0.f, 0.f);
        int i = 0;
        for (; i + 4 <= deg; i += 4) {
            int   sI[4];
            float w0v[4], w1v[4];
            #pragma unroll
            for (int u = 0; u < 4; u++) {
                sI[u] = colsrc[base + i + u];                       // uniform -> broadcast
                float4 w4 = *(const float4*)&ew[(size_t)(base + i + u) * 4];
                w0v[u] = (lo ? w4.x : w4.y) * is0;
                w1v[u] = (lo ? w4.z : w4.w) * is1;
            }
            #pragma unroll
            for (int u = 0; u < 4; u++) {
                const float* fs = feat + (size_t)sI[u] * 256;
                float4 f0 = *(const float4*)&fs[c0];
                float4 f1 = *(const float4*)&fs[c1];
                a0.x += f0.x * w0v[u]; a0.y += f0.y * w0v[u];
                a0.z += f0.z * w0v[u]; a0.w += f0.w * w0v[u];
                a1.x += f1.x * w1v[u]; a1.y += f1.y * w1v[u];
                a1.z += f1.z * w1v[u]; a1.w += f1.w * w1v[u];
            }
        }
        for (; i < deg; i++) {
            int s = colsrc[base + i];
            float4 w4 = *(const float4*)&ew[(size_t)(base + i) * 4];
            float w0 = (lo ? w4.x : w4.y) * is0;
            float w1 = (lo ? w4.z : w4.w) * is1;
            const float* fs = feat + (size_t)s * 256;
            float4 f0 = *(const float4*)&fs[c0];
            float4 f1 = *(const float4*)&fs[c1];
            a0.x += f0.x * w0; a0.y += f0.y * w0; a0.z += f0.z * w0; a0.w += f0.w * w0;
            a1.x += f1.x * w1; a1.y += f1.y * w1; a1.z += f1.z * w1; a1.w += f1.w * w1;
        }
        float4 b0 = *(const float4*)&bias[c0];
        float4 b1 = *(const float4*)&bias[c1];
        a0.x += b0.x; a0.y += b0.y; a0.z += b0.z; a0.w += b0.w;
        a1.x += b1.x; a1.y += b1.y; a1.z += b1.z; a1.w += b1.w;
        if (RELU) {
            a0.x = fmaxf(a0.x, 0.f); a0.y = fmaxf(a0.y, 0.f);
            a0.z = fmaxf(a0.z, 0.f); a0.w = fmaxf(a0.w, 0.f);
            a1.x = fmaxf(a1.x, 0.f); a1.y = fmaxf(a1.y, 0.f);
            a1.z = fmaxf(a1.z, 0.f); a1.w = fmaxf(a1.w, 0.f);
        }
        *(float4*)&out[(size_t)n * 256 + c0] = a0;
        *(float4*)&out[(size_t)n * 256 + c1] = a1;
    } else {  // HD == 64, H == 1
        const int c0 = lane * 2;
        float2 a = make_float2(0.f, 0.f);
        int i = 0;
        for (; i + 4 <= deg; i += 4) {
            int   sI[4];
            float wv[4];
            #pragma unroll
            for (int u = 0; u < 4; u++) {
                sI[u] = colsrc[base + i + u];
                wv[u] = ew[base + i + u] * sh[0];
            }
            #pragma unroll
            for (int u = 0; u < 4; u++) {
                float2 f = *(const float2*)&feat[(size_t)sI[u] * 64 + c0];
                a.x += f.x * wv[u];
                a.y += f.y * wv[u];
            }
        }
        for (; i < deg; i++) {
            int s = colsrc[base + i];
            float w = ew[base + i] * sh[0];
            float2 f = *(const float2*)&feat[(size_t)s * 64 + c0];
            a.x += f.x * w;
            a.y += f.y * w;
        }
        a.x += bias[c0];
        a.y += bias[c0 + 1];
        if (RELU) { a.x = fmaxf(a.x, 0.f); a.y = fmaxf(a.y, 0.f); }
        *(float2*)&out[(size_t)n * 64 + c0] = a;
    }
}

// ---------------------------------------------------------------------------
// kernel_launch
// ---------------------------------------------------------------------------
extern "C" void kernel_launch(void* const* d_in, const int* in_sizes, int n_in,
                              void* d_out, int out_size) {
    const float* features = (const float*)d_in[0];
    const int*   src      = (const int*)d_in[1];
    const int*   dst      = (const int*)d_in[2];
    const float* W1  = (const float*)d_in[3];
    const float* al1 = (const float*)d_in[4];
    const float* ar1 = (const float*)d_in[5];
    const float* b1  = (const float*)d_in[6];
    const float* W2  = (const float*)d_in[7];
    const float* al2 = (const float*)d_in[8];
    const float* ar2 = (const float*)d_in[9];
    const float* b2  = (const float*)d_in[10];
    const float* W3  = (const float*)d_in[11];
    const float* al3 = (const float*)d_in[12];
    const float* ar3 = (const float*)d_in[13];
    const float* b3  = (const float*)d_in[14];

    const int N = in_sizes[0] / 128;
    const int E = in_sizes[1];

    float *feat, *bufA, *bufB, *el, *er, *ew;
    int *rowptr, *cursor, *cnt, *colsrc;
    cudaGetSymbolAddress((void**)&feat,   g_feat);
    cudaGetSymbolAddress((void**)&bufA,   g_bufA);
    cudaGetSymbolAddress((void**)&bufB,   g_bufB);
    cudaGetSymbolAddress((void**)&el,     g_el);
    cudaGetSymbolAddress((void**)&er,     g_er);
    cudaGetSymbolAddress((void**)&ew,     g_ew);
    cudaGetSymbolAddress((void**)&rowptr, g_rowptr);
    cudaGetSymbolAddress((void**)&cursor, g_cursor);
    cudaGetSymbolAddress((void**)&cnt,    g_cnt);
    cudaGetSymbolAddress((void**)&colsrc, g_colsrc);

    // --- CSR by dst ---
    cudaMemsetAsync(cnt, 0, (size_t)N * sizeof(int));
    hist_kernel<<<(E + 255) / 256, 256>>>(dst, cnt, E);
    scan_kernel<<<1, 1024>>>(cnt, rowptr, cursor, N, E);
    scatter_kernel<<<(E + 255) / 256, 256>>>(src, dst, cursor, colsrc, E);

    const int warpsGrid = (N + 7) / 8;  // 8 warps (256 thr) per block

    // --- Layer 1: IN=128 -> H*D=256 ---
    {
        dim3 grid(256 / 64, (N + 127) / 128);
        sgemm_kernel<<<grid, 256>>>(features, W1, feat, N, 128, 256);
        elr_kernel<4, 64><<<warpsGrid, 256>>>(feat, al1, ar1, el, er, N);
        agg_kernel<4, 64, true><<<warpsGrid, 256>>>(feat, el, er, b1, rowptr, colsrc, ew, bufA, N);
    }
    // --- Layer 2: 256 -> 256 ---
    {
        dim3 grid(256 / 64, (N + 127) / 128);
        sgemm_kernel<<<grid, 256>>>(bufA, W2, feat, N, 256, 256);
        elr_kernel<4, 64><<<warpsGrid, 256>>>(feat, al2, ar2, el, er, N);
        agg_kernel<4, 64, true><<<warpsGrid, 256>>>(feat, el, er, b2, rowptr, colsrc, ew, bufB, N);
    }
    // --- Layer 3: 256 -> 64 (H=1); mean over 1 head == identity ---
    {
        dim3 grid(64 / 64, (N + 127) / 128);
        sgemm_kernel<<<grid, 256>>>(bufB, W3, feat, N, 256, 64);
        elr_kernel<1, 64><<<warpsGrid, 256>>>(feat, al3, ar3, el, er, N);
        agg_kernel<1, 64, false><<<warpsGrid, 256>>>(feat, el, er, b3, rowptr, colsrc, ew,
                                                     (float*)d_out, N);
    }
}